// round 7
// baseline (speedup 1.0000x reference)
#include <cuda_runtime.h>
#include <cuda_fp16.h>

// SmileMoENorm — R6 (packed-fp16 affine + PDL + streaming hints) with
// Blackwell 256-bit global accesses.
//
// sm_100a+ supports ld/st.global.v8.f32 (LDG.E.256 / STG.E.256). Using them
// halves the memory-instruction count per token (4 loads + 4 stores instead
// of 8+8), cutting issue pressure and presenting 1KB-contiguous warp
// accesses to the LSU. Structure is otherwise frozen at R6: one warp per
// token, full row cached in registers (single global read), fp16-packed
// (gamma,beta) table built by a PDL-overlapped pre-pass.

#define N_TOKENS    131072
#define HIDDEN      1024
#define NUM_EXPERTS 8
#define H4          (HIDDEN / 4)
#define EPS         1e-5f

__device__ __half2 d_pk[NUM_EXPERTS * HIDDEN];   // (gamma, beta) per element

// ---- 256-bit global access helpers (Blackwell) -----------------------------
__device__ __forceinline__ void ldg256_cs(const float* p, float* r) {
    asm volatile("ld.global.cs.v8.f32 {%0,%1,%2,%3,%4,%5,%6,%7}, [%8];"
                 : "=f"(r[0]), "=f"(r[1]), "=f"(r[2]), "=f"(r[3]),
                   "=f"(r[4]), "=f"(r[5]), "=f"(r[6]), "=f"(r[7])
                 : "l"(p));
}
__device__ __forceinline__ void stg256_cs(float* p, const float* r) {
    asm volatile("st.global.cs.v8.f32 [%0], {%1,%2,%3,%4,%5,%6,%7,%8};"
                 :: "l"(p),
                    "f"(r[0]), "f"(r[1]), "f"(r[2]), "f"(r[3]),
                    "f"(r[4]), "f"(r[5]), "f"(r[6]), "f"(r[7])
                 : "memory");
}

// ---- pre-pass: pack gamma/beta into fp16 ----------------------------------
__global__ void k_pack(const float* __restrict__ gamma,
                       const float* __restrict__ beta) {
    const int i = blockIdx.x * blockDim.x + threadIdx.x;   // 0..8191
    d_pk[i] = __floats2half2_rn(gamma[i], beta[i]);
}

// ------------------------------------------------------------- main kernel
__global__ __launch_bounds__(256, 4)
void smile_moe_norm_kernel(const float* __restrict__ x,
                           const float4* __restrict__ logits4,   // [N,2] float4
                           float* __restrict__ out) {
    const int warp_in_block = threadIdx.x >> 5;
    const int lane          = threadIdx.x & 31;
    const int token         = blockIdx.x * (blockDim.x >> 5) + warp_in_block;

    // ---- router: top-2 of 8 logits, renormalized softmax weights ----------
    const float4 la = __ldg(&logits4[token * 2 + 0]);
    const float4 lb = __ldg(&logits4[token * 2 + 1]);
    float l[NUM_EXPERTS] = { la.x, la.y, la.z, la.w, lb.x, lb.y, lb.z, lb.w };

    float best = l[0], second = -3.4e38f;
    int   e0 = 0,     e1 = 0;
    #pragma unroll
    for (int i = 1; i < NUM_EXPERTS; i++) {
        float v = l[i];
        if (v > best)        { second = best; e1 = e0; best = v; e0 = i; }
        else if (v > second) { second = v; e1 = i; }
    }
    const float t  = __expf(second - best);     // full-softmax denom cancels
    const float w0 = 1.0f / (1.0f + t);
    const float w1 = 1.0f - w0;
    const __half2 w0h = __float2half2_rn(w0);
    const __half2 w1h = __float2half2_rn(w1);

    // ---- row pass: 4 x 256-bit loads, warp reduction ------------------------
    // thread owns elements {k*256 + lane*8 .. +7}, k = 0..3
    const float* xr = x + (size_t)token * HIDDEN;
    float v[32];
    float sum = 0.0f, sq = 0.0f;
    #pragma unroll
    for (int k = 0; k < 4; k++) {
        ldg256_cs(xr + k * 256 + lane * 8, v + k * 8);
        #pragma unroll
        for (int j = 0; j < 8; j++) {
            const float f = v[k * 8 + j];
            sum += f;
            sq = fmaf(f, f, sq);
        }
    }
    #pragma unroll
    for (int off = 16; off > 0; off >>= 1) {
        sum += __shfl_xor_sync(0xFFFFFFFFu, sum, off);
        sq  += __shfl_xor_sync(0xFFFFFFFFu, sq,  off);
    }
    const float mean = sum * (1.0f / HIDDEN);
    const float var  = fmaf(-mean, mean, sq * (1.0f / HIDDEN));
    const float rstd = rsqrtf(var + EPS);
    const float mr   = -mean * rstd;            // normed = x*rstd + mr

    // PDL: d_pk is written by k_pack; wait only now (latency hidden).
    cudaGridDependencySynchronize();

    // ---- epilogue: packed-fp16 blended affine + 256-bit streaming stores ----
    const __half2* pk0 = d_pk + e0 * HIDDEN;
    const __half2* pk1 = d_pk + e1 * HIDDEN;
    float* orow = out + (size_t)token * HIDDEN;

    #pragma unroll
    for (int k = 0; k < 4; k++) {
        const int h = k * 256 + lane * 8;       // first of 8 elements
        // 8 (g,b) half2 per expert = 32B = 2 x uint4 per expert (L1 hits)
        const uint4 a0 = *(const uint4*)(pk0 + h);
        const uint4 a1 = *(const uint4*)(pk0 + h + 4);
        const uint4 b0 = *(const uint4*)(pk1 + h);
        const uint4 b1 = *(const uint4*)(pk1 + h + 4);
        const unsigned pa[8] = { a0.x, a0.y, a0.z, a0.w, a1.x, a1.y, a1.z, a1.w };
        const unsigned pb[8] = { b0.x, b0.y, b0.z, b0.w, b1.x, b1.y, b1.z, b1.w };

        float o[8];
        #pragma unroll
        for (int j = 0; j < 8; j++) {
            const __half2 ga = *(const __half2*)&pa[j];
            const __half2 gb = *(const __half2*)&pb[j];
            const float2 fb = __half22float2(__hfma2(ga, w0h, __hmul2(gb, w1h)));
            const float n = fmaf(v[k * 8 + j], rstd, mr);
            o[j] = fmaf(n, fb.x, fb.y);
        }
        stg256_cs(orow + h, o);
    }
}

// ------------------------------------------------------------------ launch
extern "C" void kernel_launch(void* const* d_in, const int* in_sizes, int n_in,
                              void* d_out, int out_size) {
    const float*  x       = (const float*)d_in[0];   // hidden_states [N, H]
    const float4* logits4 = (const float4*)d_in[1];  // router_logits [N, 8]
    const float*  gamma   = (const float*)d_in[2];   // [E, H]
    const float*  beta    = (const float*)d_in[3];   // [E, H]
    float* out            = (float*)d_out;

    k_pack<<<(NUM_EXPERTS * HIDDEN) / 256, 256>>>(gamma, beta);

    cudaLaunchConfig_t cfg = {};
    cfg.gridDim  = dim3(N_TOKENS / 8, 1, 1);         // 8 warps/block
    cfg.blockDim = dim3(256, 1, 1);
    cudaLaunchAttribute attr[1];
    attr[0].id = cudaLaunchAttributeProgrammaticStreamSerialization;
    attr[0].val.programmaticStreamSerializationAllowed = 1;
    cfg.attrs = attr;
    cfg.numAttrs = 1;
    cudaLaunchKernelEx(&cfg, smile_moe_norm_kernel, x, logits4, out);
}